// round 2
// baseline (speedup 1.0000x reference)
#include <cuda_runtime.h>

#define Bsz 64
#define Ksz 1000
#define MAXIT 50
#define THRESH 1e-3f
#define C20 2.0611536224385578e-9f   /* exp(-20.0f) */
#define LOGCLAMP -18.420680743952367f /* log(1e-8) */

// ---------- device scratch (no allocations allowed) ----------
__device__ float d_la[Bsz * Ksz];
__device__ float d_lb[Bsz * Ksz];
__device__ float d_EU[Bsz * Ksz];
__device__ float d_EV[Bsz * Ksz];
__device__ float d_ce[Bsz];
__device__ float d_cost[Bsz];
__device__ unsigned d_err[MAXIT];
__device__ unsigned d_cnt[MAXIT];

// ---------- reductions (256-thread blocks) ----------
__device__ __forceinline__ float warpSum(float v) {
#pragma unroll
    for (int o = 16; o > 0; o >>= 1) v += __shfl_down_sync(0xffffffffu, v, o);
    return v;
}
__device__ __forceinline__ float warpMax(float v) {
#pragma unroll
    for (int o = 16; o > 0; o >>= 1) v = fmaxf(v, __shfl_down_sync(0xffffffffu, v, o));
    return v;
}
__device__ float blockSum256(float v) {
    __shared__ float sc[8];
    __shared__ float res;
    int tid = threadIdx.x, w = tid >> 5, l = tid & 31;
    v = warpSum(v);
    if (l == 0) sc[w] = v;
    __syncthreads();
    if (w == 0) {
        float x = (l < 8) ? sc[l] : 0.f;
        x = warpSum(x);
        if (l == 0) res = x;
    }
    __syncthreads();
    float r = res;
    __syncthreads();
    return r;
}
__device__ float blockMax256(float v) {
    __shared__ float sc[8];
    __shared__ float res;
    int tid = threadIdx.x, w = tid >> 5, l = tid & 31;
    v = warpMax(v);
    if (l == 0) sc[w] = v;
    __syncthreads();
    if (w == 0) {
        float x = (l < 8) ? sc[l] : -1e30f;
        x = warpMax(x);
        if (l == 0) res = x;
    }
    __syncthreads();
    float r = res;
    __syncthreads();
    return r;
}

// ---------- kernel 1: softmaxes -> la/lb, CE per-row, zero barrier slots ----------
__global__ void __launch_bounds__(256) setup_kernel(
    const float* __restrict__ sl, const float* __restrict__ tl,
    const int* __restrict__ labels) {
    int bx = blockIdx.x, tid = threadIdx.x;
    if (bx == 0 && tid < MAXIT) { d_err[tid] = 0u; d_cnt[tid] = 0u; }

    bool isS = (bx >= Bsz);
    int b = isS ? bx - Bsz : bx;
    const float* x = (isS ? sl : tl) + (size_t)b * Ksz;

    float lm = -1e30f;
    for (int j = tid; j < Ksz; j += 256) lm = fmaxf(lm, x[j]);
    float m = blockMax256(lm);

    float ls = 0.f;
    for (int j = tid; j < Ksz; j += 256) ls += __expf((x[j] - m) * 0.25f);
    float s = blockSum256(ls);
    float logs = __logf(s);

    float* dst = isS ? d_lb : d_la;
    for (int j = tid; j < Ksz; j += 256)
        dst[b * Ksz + j] = fmaxf((x[j] - m) * 0.25f - logs, LOGCLAMP);

    if (isS) {
        float ls2 = 0.f;
        for (int j = tid; j < Ksz; j += 256) ls2 += __expf(x[j] - m);
        float s2 = blockSum256(ls2);
        if (tid == 0) {
            float xl = x[labels[b]];
            d_ce[b] = -((xl - m) - __logf(s2));
        }
    }
}

// ---------- kernel 2: Sinkhorn, 64 co-resident blocks, spin grid barrier ----------
__global__ void __launch_bounds__(256) sinkhorn_kernel() {
    int b = blockIdx.x, tid = threadIdx.x;
    __shared__ float la_s[Ksz], lb_s[Ksz], f_s[Ksz], g_s[Ksz];
    __shared__ float sh_err;

    for (int j = tid; j < Ksz; j += 256) {
        la_s[j] = d_la[b * Ksz + j];
        lb_s[j] = d_lb[b * Ksz + j];
        f_s[j] = 0.f;
        g_s[j] = 0.f;
    }
    __syncthreads();

    for (int t = 0; t < MAXIT; t++) {
        // f-half: f_new_i = -log( e^-20 * S + exp(g_i + lb_i) ),  S = sum_j exp(g_j+lb_j)
        float Wr[4];
        float ls = 0.f;
#pragma unroll
        for (int k = 0; k < 4; k++) {
            int j = tid + k * 256;
            if (j < Ksz) { float e = __expf(g_s[j] + lb_s[j]); Wr[k] = e; ls += e; }
        }
        float S = blockSum256(ls);
        float E = S * C20;
        float le = 0.f;
#pragma unroll
        for (int k = 0; k < 4; k++) {
            int j = tid + k * 256;
            if (j < Ksz) {
                float fn = -__logf(E + Wr[k]);
                le = fmaxf(le, fabsf(fn - f_s[j]));
                f_s[j] = fn;
            }
        }
        float err = blockMax256(le);
        if (tid == 0) atomicMax(&d_err[t], __float_as_uint(err));

        // g-half
        ls = 0.f;
#pragma unroll
        for (int k = 0; k < 4; k++) {
            int j = tid + k * 256;
            if (j < Ksz) { float e = __expf(f_s[j] + la_s[j]); Wr[k] = e; ls += e; }
        }
        float T2 = blockSum256(ls);
        float E2 = T2 * C20;
#pragma unroll
        for (int k = 0; k < 4; k++) {
            int j = tid + k * 256;
            if (j < Ksz) g_s[j] = -__logf(E2 + Wr[k]);
        }

        // grid barrier + global done check (per-iteration slots: no reset races)
        __syncthreads();
        if (tid == 0) {
            __threadfence();
            atomicAdd(&d_cnt[t], 1u);
            while (atomicAdd(&d_cnt[t], 0u) < (unsigned)Bsz) __nanosleep(64);
            __threadfence();
            sh_err = __uint_as_float(*((volatile unsigned*)&d_err[t]));
        }
        __syncthreads();
        if (sh_err < THRESH) break;
    }

    // epilogue: EU/EV and closed-form per-row OT cost
    float su = 0.f, sv = 0.f, dt = 0.f;
    for (int j = tid; j < Ksz; j += 256) {
        float eu = __expf(f_s[j] + la_s[j]);
        float ev = __expf(g_s[j] + lb_s[j]);
        d_EU[b * Ksz + j] = eu;
        d_EV[b * Ksz + j] = ev;
        su += eu; sv += ev; dt += eu * ev;
    }
    su = blockSum256(su);
    sv = blockSum256(sv);
    dt = blockSum256(dt);
    if (tid == 0) d_cost[b] = C20 * (su * sv - dt);
}

// ---------- kernel 3: write the 256MB transport plan (scaled outer product) ----------
__global__ void __launch_bounds__(256) plan_kernel(float* __restrict__ out) {
    int bx = blockIdx.x;
    int b = bx / 125;
    int chunk = bx % 125;
    int i0 = chunk * 8;
    int tid = threadIdx.x;

    __shared__ float sEU[8];
    if (tid < 8) sEU[tid] = d_EU[b * Ksz + i0 + tid];
    float ev[4];
#pragma unroll
    for (int k = 0; k < 4; k++) {
        int j = tid + k * 256;
        ev[k] = (j < Ksz) ? d_EV[b * Ksz + j] : 0.f;
    }
    __syncthreads();

    float* base = out + ((size_t)b * Ksz + i0) * (size_t)Ksz;
#pragma unroll
    for (int r = 0; r < 8; r++) {
        float u = sEU[r];
        float sc = u * C20;
        int i = i0 + r;
        float* row = base + (size_t)r * Ksz;
#pragma unroll
        for (int k = 0; k < 4; k++) {
            int j = tid + k * 256;
            if (j < Ksz) {
                float val = (j == i) ? u * ev[k] : sc * ev[k];
                row[j] = val;
            }
        }
    }
}

// ---------- kernel 4: scalars ----------
__global__ void finalize_kernel(float* __restrict__ out) {
    int tid = threadIdx.x;  // 64 threads
    float ce = d_ce[tid], ct = d_cost[tid];
#pragma unroll
    for (int o = 16; o > 0; o >>= 1) {
        ce += __shfl_down_sync(0xffffffffu, ce, o);
        ct += __shfl_down_sync(0xffffffffu, ct, o);
    }
    __shared__ float a[2], c[2];
    int w = tid >> 5, l = tid & 31;
    if (l == 0) { a[w] = ce; c[w] = ct; }
    __syncthreads();
    if (tid == 0) {
        float ceS = (a[0] + a[1]) * (1.f / 64.f);
        float ot = (c[0] + c[1]) * (1.f / 64.f);
        out[0] = ceS + 0.5f * ot;  // total_loss
        out[1] = ot;               // ot_loss
        out[2] = ceS;              // ce_loss
    }
}

extern "C" void kernel_launch(void* const* d_in, const int* in_sizes, int n_in,
                              void* d_out, int out_size) {
    const float* sl = (const float*)d_in[0];      // student_logits [64,1000]
    const float* tl = (const float*)d_in[1];      // teacher_logits [64,1000]
    const int* labels = (const int*)d_in[2];      // labels [64]
    float* out = (float*)d_out;

    long long planOff = (long long)out_size - (long long)Bsz * Ksz * Ksz;
    if (planOff < 0) planOff = 3;

    setup_kernel<<<2 * Bsz, 256>>>(sl, tl, labels);
    sinkhorn_kernel<<<Bsz, 256>>>();
    plan_kernel<<<Bsz * 125, 256>>>(out + planOff);
    finalize_kernel<<<1, 64>>>(out);
}

// round 4
// speedup vs baseline: 3.4639x; 3.4639x over previous
#include <cuda_runtime.h>

#define Bsz 64
#define Ksz 1000
#define MAXIT 50
#define THRESH 1e-3f
#define C20 2.0611536224385578e-9f   /* exp(-20.0f) */
#define CLMIN 1e-8f

// ---------- device scratch (no allocations allowed) ----------
__device__ float d_A[Bsz * Ksz];            // clamped teacher probs (= exp(log_a))
__device__ float d_B[Bsz * Ksz];            // clamped student probs (= exp(log_b))
__device__ float d_EU[Bsz * Ksz];
__device__ float d_EV[Bsz * Ksz];
__device__ float d_hist[MAXIT * Bsz * Ksz]; // EU snapshot per iteration (12.8MB)
__device__ float d_Tsum[MAXIT * Bsz];       // sum(EU) per (iter,row)
__device__ unsigned d_err[MAXIT];           // global max err per iteration (as uint)
__device__ float d_ce[Bsz];
__device__ float d_cost[Bsz];
__device__ unsigned d_done_cnt;

__device__ __forceinline__ float fastrcp(float x) {
    float r;
    asm("rcp.approx.f32 %0, %1;" : "=f"(r) : "f"(x));
    return r;
}

// ---------- warp reductions ----------
__device__ __forceinline__ float warpSumX(float v) {
#pragma unroll
    for (int o = 16; o > 0; o >>= 1) v += __shfl_xor_sync(0xffffffffu, v, o);
    return v;
}
__device__ __forceinline__ float warpMaxX(float v) {
#pragma unroll
    for (int o = 16; o > 0; o >>= 1) v = fmaxf(v, __shfl_xor_sync(0xffffffffu, v, o));
    return v;
}

// block reductions for 256 threads, ONE __syncthreads each (leader-write, all-read-8)
__device__ __forceinline__ float blockSum1bar(float v, float* sc) {
    int w = threadIdx.x >> 5;
    v = warpSumX(v);
    if ((threadIdx.x & 31) == 0) sc[w] = v;
    __syncthreads();
    float r = sc[0];
#pragma unroll
    for (int i = 1; i < 8; i++) r += sc[i];
    return r;
}
__device__ __forceinline__ void blockRed3_1bar(float& s, float& mx, float& mn,
                                               float* sS, float* sMx, float* sMn) {
    int w = threadIdx.x >> 5, l = threadIdx.x & 31;
#pragma unroll
    for (int o = 16; o > 0; o >>= 1) {
        s += __shfl_xor_sync(0xffffffffu, s, o);
        mx = fmaxf(mx, __shfl_xor_sync(0xffffffffu, mx, o));
        mn = fminf(mn, __shfl_xor_sync(0xffffffffu, mn, o));
    }
    if (l == 0) { sS[w] = s; sMx[w] = mx; sMn[w] = mn; }
    __syncthreads();
    float rs = sS[0], rmx = sMx[0], rmn = sMn[0];
#pragma unroll
    for (int i = 1; i < 8; i++) {
        rs += sS[i];
        rmx = fmaxf(rmx, sMx[i]);
        rmn = fminf(rmn, sMn[i]);
    }
    s = rs; mx = rmx; mn = rmn;
}
__device__ __forceinline__ void blockSum3_1bar(float& a, float& b, float& c,
                                               float* sA, float* sB, float* sC) {
    int w = threadIdx.x >> 5, l = threadIdx.x & 31;
#pragma unroll
    for (int o = 16; o > 0; o >>= 1) {
        a += __shfl_xor_sync(0xffffffffu, a, o);
        b += __shfl_xor_sync(0xffffffffu, b, o);
        c += __shfl_xor_sync(0xffffffffu, c, o);
    }
    if (l == 0) { sA[w] = a; sB[w] = b; sC[w] = c; }
    __syncthreads();
    float ra = sA[0], rb = sB[0], rc = sC[0];
#pragma unroll
    for (int i = 1; i < 8; i++) { ra += sA[i]; rb += sB[i]; rc += sC[i]; }
    a = ra; b = rb; c = rc;
}

// legacy full block sum/max with broadcast (setup kernel only)
__device__ float blockSum256(float v) {
    __shared__ float sc[8];
    int w = threadIdx.x >> 5, l = threadIdx.x & 31;
    v = warpSumX(v);
    if (l == 0) sc[w] = v;
    __syncthreads();
    float r = sc[0];
#pragma unroll
    for (int i = 1; i < 8; i++) r += sc[i];
    __syncthreads();
    return r;
}
__device__ float blockMax256(float v) {
    __shared__ float sc[8];
    int w = threadIdx.x >> 5, l = threadIdx.x & 31;
    v = warpMaxX(v);
    if (l == 0) sc[w] = v;
    __syncthreads();
    float r = sc[0];
#pragma unroll
    for (int i = 1; i < 8; i++) r = fmaxf(r, sc[i]);
    __syncthreads();
    return r;
}

// ---------- kernel 1: softmaxes -> A/B (clamped probs), CE; zero flags ----------
__global__ void __launch_bounds__(256) setup_kernel(
    const float* __restrict__ sl, const float* __restrict__ tl,
    const int* __restrict__ labels) {
    int bx = blockIdx.x, tid = threadIdx.x;
    if (bx == 0) {
        if (tid < MAXIT) d_err[tid] = 0u;
        if (tid == 0) d_done_cnt = 0u;
    }

    bool isS = (bx >= Bsz);
    int b = isS ? bx - Bsz : bx;
    const float* x = (isS ? sl : tl) + (size_t)b * Ksz;

    float lm = -1e30f;
    for (int j = tid; j < Ksz; j += 256) lm = fmaxf(lm, x[j]);
    float m = blockMax256(lm);

    float ls = 0.f;
    for (int j = tid; j < Ksz; j += 256) ls += __expf((x[j] - m) * 0.25f);
    float s = blockSum256(ls);
    float rs = __fdividef(1.0f, s);

    float* dst = isS ? d_B : d_A;
    for (int j = tid; j < Ksz; j += 256)
        dst[b * Ksz + j] = fmaxf(__expf((x[j] - m) * 0.25f) * rs, CLMIN);

    if (isS) {
        float ls2 = 0.f;
        for (int j = tid; j < Ksz; j += 256) ls2 += __expf(x[j] - m);
        float s2 = blockSum256(ls2);
        if (tid == 0) {
            float xl = x[labels[b]];
            d_ce[b] = -((xl - m) - __logf(s2));
        }
    }
}

// ---------- kernel 2: Sinkhorn, 64 independent blocks, NO inter-block sync ----------
__global__ void __launch_bounds__(256) sinkhorn_kernel() {
    int b = blockIdx.x, tid = threadIdx.x;
    __shared__ float sS[8], sMx[8], sMn[8], sT[8];

    bool act = tid < 250;  // 4 elems/thread, 250*4 = 1000
    int j0 = tid * 4;

    float A[4], Bv[4], EU[4], EV[4], Dp[4];
    if (act) {
        float4 a4 = *(const float4*)(d_A + b * Ksz + j0);
        float4 b4 = *(const float4*)(d_B + b * Ksz + j0);
        A[0] = a4.x; A[1] = a4.y; A[2] = a4.z; A[3] = a4.w;
        Bv[0] = b4.x; Bv[1] = b4.y; Bv[2] = b4.z; Bv[3] = b4.w;
    } else {
#pragma unroll
        for (int k = 0; k < 4; k++) { A[k] = 0.f; Bv[k] = 0.f; }
    }
#pragma unroll
    for (int k = 0; k < 4; k++) { EV[k] = Bv[k]; Dp[k] = 1.0f; }

    // initial S = sum(B) over the row
    float ls = EV[0] + EV[1] + EV[2] + EV[3];
    float S = blockSum1bar(ls, sS);
    __syncthreads();  // protect sS reuse

    for (int t = 0; t < MAXIT; t++) {
        // ----- f-half: EU = A * rcp(c20*S + EV); ratio = D_old * rcp(D_new) -----
        float lsum = 0.f, lmax = -1e30f, lmin = 1e30f;
#pragma unroll
        for (int k = 0; k < 4; k++) {
            float Dn = fmaf(C20, S, EV[k]);
            float rc = fastrcp(Dn);
            EU[k] = A[k] * rc;
            if (act) {
                float ratio = Dp[k] * rc;
                lmax = fmaxf(lmax, ratio);
                lmin = fminf(lmin, ratio);
            }
            Dp[k] = Dn;
            lsum += EU[k];
        }
        blockRed3_1bar(lsum, lmax, lmin, sS, sMx, sMn);
        float T = lsum;
        if (tid == 0) {
            d_Tsum[t * Bsz + b] = T;
            float err = fmaxf(fabsf(__logf(lmax)), fabsf(__logf(lmin)));
            atomicMax(&d_err[t], __float_as_uint(err));
        }
        // snapshot EU (fire-and-forget)
        if (act)
            *(float4*)(d_hist + ((size_t)(t * Bsz + b)) * Ksz + j0) =
                make_float4(EU[0], EU[1], EU[2], EU[3]);

        // ----- g-half: EV = B * rcp(c20*T + EU) -----
        float ls2 = 0.f;
#pragma unroll
        for (int k = 0; k < 4; k++) {
            float Eg = fmaf(C20, T, EU[k]);
            EV[k] = Bv[k] * fastrcp(Eg);
            ls2 += EV[k];
        }
        S = blockSum1bar(ls2, sT);
        // no extra bar needed: next use of sS/sMx/sMn is after this bar's
        // release and every thread's reads of them happened before arriving here
    }
}

// ---------- kernel 3: pick stop iteration T, build EU/EV, per-row cost, scalars ----------
__global__ void __launch_bounds__(256) epilogue_kernel(float* __restrict__ out) {
    int b = blockIdx.x, tid = threadIdx.x;
    __shared__ float sA[8], sB[8], sC[8];
    __shared__ int sDone;

    // every block independently (and identically) derives the stop iteration
    int T = MAXIT - 1;
    for (int t = 0; t < MAXIT; t++) {
        if (__uint_as_float(d_err[t]) < THRESH) { T = t; break; }
    }

    bool act = tid < 250;
    int j0 = tid * 4;
    float Ts = d_Tsum[T * Bsz + b];

    float su = 0.f, sv = 0.f, dt = 0.f;
    float EU[4], EV[4];
    if (act) {
        float4 u4 = *(const float4*)(d_hist + ((size_t)(T * Bsz + b)) * Ksz + j0);
        float4 b4 = *(const float4*)(d_B + b * Ksz + j0);
        EU[0] = u4.x; EU[1] = u4.y; EU[2] = u4.z; EU[3] = u4.w;
        float Bv[4] = {b4.x, b4.y, b4.z, b4.w};
#pragma unroll
        for (int k = 0; k < 4; k++) {
            float Eg = fmaf(C20, Ts, EU[k]);
            EV[k] = Bv[k] * fastrcp(Eg);
            su += EU[k]; sv += EV[k]; dt += EU[k] * EV[k];
        }
        *(float4*)(d_EU + b * Ksz + j0) = make_float4(EU[0], EU[1], EU[2], EU[3]);
        *(float4*)(d_EV + b * Ksz + j0) = make_float4(EV[0], EV[1], EV[2], EV[3]);
    }
    blockSum3_1bar(su, sv, dt, sA, sB, sC);
    if (tid == 0) {
        d_cost[b] = C20 * (su * sv - dt);
        __threadfence();
        unsigned old = atomicAdd(&d_done_cnt, 1u);
        sDone = (old == Bsz - 1) ? 1 : 0;
    }
    __syncthreads();
    if (sDone) {
        // last block computes the three scalar outputs
        float ce = 0.f, ct = 0.f;
        if (tid < Bsz) { ce = d_ce[tid]; ct = d_cost[tid]; }
        blockSum3_1bar(ce, ct, su, sA, sB, sC);  // third value unused
        if (tid == 0) {
            float ceS = ce * (1.f / 64.f);
            float ot = ct * (1.f / 64.f);
            out[0] = ceS + 0.5f * ot;
            out[1] = ot;
            out[2] = ceS;
        }
    }
}

// ---------- kernel 4: write the 256MB transport plan (scaled outer product) ----------
// 20 rows per block: grid = 64 * 50 = 3200 blocks
__global__ void __launch_bounds__(256) plan_kernel(float* __restrict__ out) {
    int bx = blockIdx.x;
    int b = bx / 50;
    int chunk = bx % 50;
    int i0 = chunk * 20;
    int tid = threadIdx.x;

    __shared__ float sEU[20];
    if (tid < 20) sEU[tid] = d_EU[b * Ksz + i0 + tid];
    float ev[4];
#pragma unroll
    for (int k = 0; k < 4; k++) {
        int j = tid + k * 256;
        ev[k] = (j < Ksz) ? d_EV[b * Ksz + j] : 0.f;
    }
    __syncthreads();

    float* base = out + ((size_t)b * Ksz + i0) * (size_t)Ksz;
#pragma unroll
    for (int r = 0; r < 20; r++) {
        float u = sEU[r];
        float sc = u * C20;
        int i = i0 + r;
        float* row = base + (size_t)r * Ksz;
#pragma unroll
        for (int k = 0; k < 4; k++) {
            int j = tid + k * 256;
            if (j < Ksz) {
                row[j] = (j == i) ? u * ev[k] : sc * ev[k];
            }
        }
    }
}

extern "C" void kernel_launch(void* const* d_in, const int* in_sizes, int n_in,
                              void* d_out, int out_size) {
    const float* sl = (const float*)d_in[0];      // student_logits [64,1000]
    const float* tl = (const float*)d_in[1];      // teacher_logits [64,1000]
    const int* labels = (const int*)d_in[2];      // labels [64]
    float* out = (float*)d_out;

    long long planOff = (long long)out_size - (long long)Bsz * Ksz * Ksz;
    if (planOff < 0) planOff = 3;

    setup_kernel<<<2 * Bsz, 256>>>(sl, tl, labels);
    sinkhorn_kernel<<<Bsz, 256>>>();
    epilogue_kernel<<<Bsz, 256>>>(out);
    plan_kernel<<<Bsz * 50, 256>>>(out + planOff);
}

// round 6
// speedup vs baseline: 3.9195x; 1.1315x over previous
#include <cuda_runtime.h>

#define Bsz 64
#define Ksz 1000
#define MAXIT 50
#define THRESH 1e-3f
#define C20 2.0611536224385578e-9f   /* exp(-20.0f) */
#define CLMIN 1e-8f

// ---------- device scratch (no allocations allowed) ----------
__device__ float d_Bprob[Bsz * Ksz];        // clamped student probs
__device__ float d_hist[MAXIT * Bsz * Ksz]; // EU snapshot per iteration (12.8MB)
__device__ float d_Tsum[MAXIT * Bsz];       // sum(EU) per (iter,row)
__device__ float d_errRow[MAXIT * Bsz];     // per-(iter,row) error, plain stores
__device__ float d_ce[Bsz];
__device__ float d_cost[Bsz];
__device__ unsigned d_done_cnt;             // self-resetting counter

__device__ __forceinline__ float fastrcp(float x) {
    float r;
    asm("rcp.approx.f32 %0, %1;" : "=f"(r) : "f"(x));
    return r;
}

// ---------- warp reductions ----------
__device__ __forceinline__ float warpSumX(float v) {
#pragma unroll
    for (int o = 16; o > 0; o >>= 1) v += __shfl_xor_sync(0xffffffffu, v, o);
    return v;
}
__device__ __forceinline__ float warpMaxX(float v) {
#pragma unroll
    for (int o = 16; o > 0; o >>= 1) v = fmaxf(v, __shfl_xor_sync(0xffffffffu, v, o));
    return v;
}

// block reductions for 256 threads, ONE __syncthreads each (leader-write, all-read-8)
__device__ __forceinline__ float blockSum1bar(float v, float* sc) {
    int w = threadIdx.x >> 5;
    v = warpSumX(v);
    if ((threadIdx.x & 31) == 0) sc[w] = v;
    __syncthreads();
    float r = sc[0];
#pragma unroll
    for (int i = 1; i < 8; i++) r += sc[i];
    return r;
}
__device__ __forceinline__ void blockRed3_1bar(float& s, float& mx, float& mn,
                                               float* sS, float* sMx, float* sMn) {
    int w = threadIdx.x >> 5, l = threadIdx.x & 31;
#pragma unroll
    for (int o = 16; o > 0; o >>= 1) {
        s += __shfl_xor_sync(0xffffffffu, s, o);
        mx = fmaxf(mx, __shfl_xor_sync(0xffffffffu, mx, o));
        mn = fminf(mn, __shfl_xor_sync(0xffffffffu, mn, o));
    }
    if (l == 0) { sS[w] = s; sMx[w] = mx; sMn[w] = mn; }
    __syncthreads();
    float rs = sS[0], rmx = sMx[0], rmn = sMn[0];
#pragma unroll
    for (int i = 1; i < 8; i++) {
        rs += sS[i];
        rmx = fmaxf(rmx, sMx[i]);
        rmn = fminf(rmn, sMn[i]);
    }
    s = rs; mx = rmx; mn = rmn;
}
__device__ __forceinline__ void blockSum3_1bar(float& a, float& b, float& c,
                                               float* sA, float* sB, float* sC) {
    int w = threadIdx.x >> 5, l = threadIdx.x & 31;
#pragma unroll
    for (int o = 16; o > 0; o >>= 1) {
        a += __shfl_xor_sync(0xffffffffu, a, o);
        b += __shfl_xor_sync(0xffffffffu, b, o);
        c += __shfl_xor_sync(0xffffffffu, c, o);
    }
    if (l == 0) { sA[w] = a; sB[w] = b; sC[w] = c; }
    __syncthreads();
    float ra = sA[0], rb = sB[0], rc = sC[0];
#pragma unroll
    for (int i = 1; i < 8; i++) { ra += sA[i]; rb += sB[i]; rc += sC[i]; }
    a = ra; b = rb; c = rc;
}
__device__ __forceinline__ void blockSum2_1bar(float& a, float& b,
                                               float* sA, float* sB) {
    int w = threadIdx.x >> 5, l = threadIdx.x & 31;
#pragma unroll
    for (int o = 16; o > 0; o >>= 1) {
        a += __shfl_xor_sync(0xffffffffu, a, o);
        b += __shfl_xor_sync(0xffffffffu, b, o);
    }
    if (l == 0) { sA[w] = a; sB[w] = b; }
    __syncthreads();
    float ra = sA[0], rb = sB[0];
#pragma unroll
    for (int i = 1; i < 8; i++) { ra += sA[i]; rb += sB[i]; }
    a = ra; b = rb;
}

// full block sum/max with broadcast + trailing bar (softmax prologue)
__device__ float blockSum256(float v) {
    __shared__ float sc[8];
    int w = threadIdx.x >> 5, l = threadIdx.x & 31;
    v = warpSumX(v);
    if (l == 0) sc[w] = v;
    __syncthreads();
    float r = sc[0];
#pragma unroll
    for (int i = 1; i < 8; i++) r += sc[i];
    __syncthreads();
    return r;
}
__device__ float blockMax256(float v) {
    __shared__ float sc[8];
    int w = threadIdx.x >> 5, l = threadIdx.x & 31;
    v = warpMaxX(v);
    if (l == 0) sc[w] = v;
    __syncthreads();
    float r = sc[0];
#pragma unroll
    for (int i = 1; i < 8; i++) r = fmaxf(r, sc[i]);
    __syncthreads();
    return r;
}

// ---------- kernel 1: fused softmax + CE + Sinkhorn (64 independent blocks) ----------
__global__ void __launch_bounds__(256) sinkhorn_fused(
    const float* __restrict__ sl, const float* __restrict__ tl,
    const int* __restrict__ labels) {
    int b = blockIdx.x, tid = threadIdx.x;
    __shared__ float sS[8], sMx[8], sMn[8], sT[8];

    bool act = tid < 250;  // 4 elems/thread, 250*4 = 1000
    int j0 = tid * 4;

    float tv[4], svv[4];
    if (act) {
        float4 t4 = *(const float4*)(tl + (size_t)b * Ksz + j0);
        float4 s4 = *(const float4*)(sl + (size_t)b * Ksz + j0);
        tv[0] = t4.x; tv[1] = t4.y; tv[2] = t4.z; tv[3] = t4.w;
        svv[0] = s4.x; svv[1] = s4.y; svv[2] = s4.z; svv[3] = s4.w;
    } else {
#pragma unroll
        for (int k = 0; k < 4; k++) { tv[k] = -1e30f; svv[k] = -1e30f; }
    }

    // ---- teacher softmax -> A ----
    float A[4], Bv[4];
    {
        float lm = fmaxf(fmaxf(tv[0], tv[1]), fmaxf(tv[2], tv[3]));
        float m = blockMax256(lm);
        float e[4], ls = 0.f;
#pragma unroll
        for (int k = 0; k < 4; k++) { e[k] = __expf((tv[k] - m) * 0.25f); ls += e[k]; }
        float s = blockSum256(ls);
        float rs = __fdividef(1.0f, s);
#pragma unroll
        for (int k = 0; k < 4; k++) A[k] = act ? fmaxf(e[k] * rs, CLMIN) : 0.f;
    }
    // ---- student softmax -> B, plus CE at temperature 1 ----
    {
        float lm = fmaxf(fmaxf(svv[0], svv[1]), fmaxf(svv[2], svv[3]));
        float m = blockMax256(lm);
        float e[4], ls = 0.f, ls1 = 0.f;
#pragma unroll
        for (int k = 0; k < 4; k++) {
            e[k] = __expf((svv[k] - m) * 0.25f);
            ls += e[k];
            ls1 += __expf(svv[k] - m);
        }
        float s = blockSum256(ls);
        float s1 = blockSum256(ls1);
        float rs = __fdividef(1.0f, s);
#pragma unroll
        for (int k = 0; k < 4; k++) Bv[k] = act ? fmaxf(e[k] * rs, CLMIN) : 0.f;
        if (tid == 0) {
            float xl = sl[(size_t)b * Ksz + labels[b]];
            d_ce[b] = -((xl - m) - __logf(s1));
        }
        if (act)
            *(float4*)(d_Bprob + b * Ksz + j0) = make_float4(Bv[0], Bv[1], Bv[2], Bv[3]);
    }

    // ---- Sinkhorn in the multiplicative domain ----
    float EU[4], EV[4], Dp[4];
#pragma unroll
    for (int k = 0; k < 4; k++) { EV[k] = Bv[k]; Dp[k] = 1.0f; }

    float ls0 = EV[0] + EV[1] + EV[2] + EV[3];
    float S = blockSum1bar(ls0, sS);
    __syncthreads();  // protect sS reuse

    for (int t = 0; t < MAXIT; t++) {
        // f-half: EU = A * rcp(c20*S + EV); err via ratio of denominators
        float lsum = 0.f, lmax = -1e30f, lmin = 1e30f;
#pragma unroll
        for (int k = 0; k < 4; k++) {
            float Dn = fmaf(C20, S, EV[k]);
            float rc = fastrcp(Dn);
            EU[k] = A[k] * rc;
            if (act) {
                float ratio = Dp[k] * rc;
                lmax = fmaxf(lmax, ratio);
                lmin = fminf(lmin, ratio);
            }
            Dp[k] = Dn;
            lsum += EU[k];
        }
        blockRed3_1bar(lsum, lmax, lmin, sS, sMx, sMn);
        float T = lsum;
        if (tid == 0) {
            d_Tsum[t * Bsz + b] = T;
            d_errRow[t * Bsz + b] = fmaxf(fabsf(__logf(lmax)), fabsf(__logf(lmin)));
        }
        if (act)
            *(float4*)(d_hist + ((size_t)(t * Bsz + b)) * Ksz + j0) =
                make_float4(EU[0], EU[1], EU[2], EU[3]);

        // g-half
        float ls2 = 0.f;
#pragma unroll
        for (int k = 0; k < 4; k++) {
            float Eg = fmaf(C20, T, EU[k]);
            EV[k] = Bv[k] * fastrcp(Eg);
            ls2 += EV[k];
        }
        S = blockSum1bar(ls2, sT);
    }
}

// ---------- kernel 2: fused stop-pick + plan write + cost + scalars ----------
// grid = 64 * 50; block (b, chunk) writes rows [chunk*20, chunk*20+20) of batch b
__global__ void __launch_bounds__(256) plan_fused(float* __restrict__ out,
                                                  float* __restrict__ plan) {
    int bx = blockIdx.x;
    int b = bx / 50;
    int chunk = bx % 50;
    int i0 = chunk * 20;
    int tid = threadIdx.x;

    __shared__ float sErrMax[MAXIT];
    __shared__ int sT;
    __shared__ float sEU[20];
    __shared__ float sA[8], sB[8], sC[8];
    __shared__ int sDone;

    // --- derive global stop iteration T (identical in every block) ---
    if (tid < MAXIT) {
        const float4* p = (const float4*)(d_errRow + tid * Bsz);
        float m = 0.f;
#pragma unroll
        for (int i = 0; i < Bsz / 4; i++) {
            float4 v = p[i];
            m = fmaxf(m, fmaxf(fmaxf(v.x, v.y), fmaxf(v.z, v.w)));
        }
        sErrMax[tid] = m;
    }
    __syncthreads();
    if (tid == 0) {
        int T = MAXIT - 1;
        for (int t = 0; t < MAXIT; t++)
            if (sErrMax[t] < THRESH) { T = t; break; }
        sT = T;
    }
    __syncthreads();
    int T = sT;

    float Ts = d_Tsum[T * Bsz + b];
    const float* histRow = d_hist + ((size_t)(T * Bsz + b)) * Ksz;
    if (tid < 20) sEU[tid] = histRow[i0 + tid];

    // --- alignment split of the 1000-col row (row stride 1000 == 0 mod 4) ---
    unsigned mis = (unsigned)(((size_t)plan) >> 2) & 3u;
    int h = (int)((4u - mis) & 3u);      // head scalars
    int nv = (Ksz - h) >> 2;             // float4 chunks
    int nrem = Ksz - h - 4 * nv;         // tail scalars

    bool isVec = tid < nv;
    int sIdx = tid - nv;                 // scalar-duty index
    bool isScl = (sIdx >= 0) && (sIdx < h + nrem);
    int c0 = isVec ? (h + 4 * tid)
                   : (isScl ? (sIdx < h ? sIdx : h + 4 * nv + (sIdx - h)) : 0);
    int nc = isVec ? 4 : (isScl ? 1 : 0);

    // --- per-thread EU(col)/EV(col) in registers, reused across 20 rows ---
    float eu_c[4], ev_c[4], evs_c[4];
    float su = 0.f, svs = 0.f, dt = 0.f;
#pragma unroll
    for (int k = 0; k < 4; k++) {
        if (k < nc) {
            int c = c0 + k;
            float e = histRow[c];
            float bp = d_Bprob[b * Ksz + c];
            float ev = bp * fastrcp(fmaf(C20, Ts, e));
            eu_c[k] = e; ev_c[k] = ev; evs_c[k] = ev * C20;
            su += e; svs += ev; dt += e * ev;
        } else { eu_c[k] = 0.f; ev_c[k] = 0.f; evs_c[k] = 0.f; }
    }
    __syncthreads();  // sEU ready

    // --- write 20 rows (streaming stores; evict-first keeps L2 for scratch) ---
    float* base = plan + ((size_t)(b * Ksz + i0)) * (size_t)Ksz;
    if (isVec) {
#pragma unroll
        for (int r = 0; r < 20; r++) {
            float u = sEU[r];
            int i = i0 + r;
            float4 v = make_float4(u * evs_c[0], u * evs_c[1],
                                   u * evs_c[2], u * evs_c[3]);
            unsigned dk = (unsigned)(i - c0);
            if (dk < 4u) ((float*)&v)[dk] = u * ev_c[dk];   // diagonal patch
            __stcs((float4*)(base + (size_t)r * Ksz + c0), v);
        }
    } else if (isScl) {
#pragma unroll
        for (int r = 0; r < 20; r++) {
            float u = sEU[r];
            int i = i0 + r;
            float val = (c0 == i) ? u * ev_c[0] : u * evs_c[0];
            __stcs(base + (size_t)r * Ksz + c0, val);
        }
    }

    // --- chunk-0 blocks: per-row cost + final scalars (self-resetting counter) ---
    if (chunk == 0) {
        blockSum3_1bar(su, svs, dt, sA, sB, sC);
        if (tid == 0) {
            d_cost[b] = C20 * (su * svs - dt);
            __threadfence();
            unsigned old = atomicAdd(&d_done_cnt, 1u);
            sDone = (old == Bsz - 1) ? 1 : 0;
        }
        __syncthreads();
        if (sDone) {
            if (tid == 0) __threadfence();
            __syncthreads();
            float ce = 0.f, ct = 0.f;
            if (tid < Bsz) { ce = d_ce[tid]; ct = d_cost[tid]; }
            blockSum2_1bar(ce, ct, sA, sB);
            if (tid == 0) {
                float ceS = ce * (1.f / 64.f);
                float ot = ct * (1.f / 64.f);
                out[0] = ceS + 0.5f * ot;
                out[1] = ot;
                out[2] = ceS;
                d_done_cnt = 0u;   // reset for next graph replay
            }
        }
    }
}

extern "C" void kernel_launch(void* const* d_in, const int* in_sizes, int n_in,
                              void* d_out, int out_size) {
    const float* sl = (const float*)d_in[0];      // student_logits [64,1000]
    const float* tl = (const float*)d_in[1];      // teacher_logits [64,1000]
    const int* labels = (const int*)d_in[2];      // labels [64]
    float* out = (float*)d_out;

    long long planOff = (long long)out_size - (long long)Bsz * Ksz * Ksz;
    if (planOff < 0) planOff = 3;

    sinkhorn_fused<<<Bsz, 256>>>(sl, tl, labels);
    plan_fused<<<Bsz * 50, 256>>>(out, out + planOff);
}